// round 13
// baseline (speedup 1.0000x reference)
#include <cuda_runtime.h>

#define NV   16000
#define PPV  32
#define CIN  10
#define NB   16000
#define BH   496
#define BW   432
#define OUTWH (BW*BH)          // 214272
#define OUTSZ (128*OUTWH)      // 27426816

// ---------------- static device scratch (no runtime allocation) ----------------
__device__ __align__(16) float g_voxelwise[NV * 64];   // [Nv][64]
__device__ __align__(16) float g_h2[NB * 512];         // [Nb][16][32]

extern __shared__ float sm_dyn[];

// mish(x) = x * tanh(softplus(x)) = x * t(t+2)/(t(t+2)+2), t = e^x
__device__ __forceinline__ float mishf(float x) {
    float t = __expf(fminf(x, 20.0f));
    float r = t * (t + 2.0f);
    return x * __fdividef(r, r + 2.0f);
}

// packed f32x2 FMA: d = a*b + d (elementwise, rn) — sm_100+ FFMA2
__device__ __forceinline__ void fma2(float2& d, const float2 a, const float2 b) {
    asm("fma.rn.f32x2 %0, %1, %2, %0;"
        : "+l"(reinterpret_cast<unsigned long long&>(d))
        : "l"(reinterpret_cast<const unsigned long long&>(a)),
          "l"(reinterpret_cast<const unsigned long long&>(b)));
}

// named barrier over 128 threads (4 contiguous warps)
__device__ __forceinline__ void barg(int id) {
    asm volatile("bar.sync %0, 128;" :: "r"(id) : "memory");
}

// ============================================================================
// Kernel 0: zero the output map
// ============================================================================
__global__ void zero_kernel(float4* __restrict__ out, int n4) {
    int i = blockIdx.x * blockDim.x + threadIdx.x;
    if (i < n4) out[i] = make_float4(0.f, 0.f, 0.f, 0.f);
}

// ============================================================================
// Kernel 1: VFE — R12 version (best measured). 2 voxels per barrier window.
// ============================================================================
#define VPB 8
#define A_W1T 0        // [10][68]
#define A_W2T 680      // [64][68]
#define A_W3T 5032
#define A_W4T 9384
#define A_GB  13736    // 4 layers x (gamma64 | beta64)
#define A_XT  14248    // 2 x [64][36]
#define A_MSK 18856    // 2 x [32]
#define A_SMEM_FLOATS 18920
#define A_SMEM_BYTES  (A_SMEM_FLOATS * 4)

template<int CINT>
__device__ __forceinline__ void fel_layer(
    const float* __restrict__ Wt, const float* __restrict__ gb,
    const float* __restrict__ xT, int p0, int o0, float (&y)[4][4])
{
    float2 acc[2][4];
    #pragma unroll
    for (int pj = 0; pj < 2; pj++)
        #pragma unroll
        for (int oi = 0; oi < 4; oi++) acc[pj][oi] = make_float2(0.f, 0.f);

    #pragma unroll 4
    for (int c = 0; c < CINT; c++) {
        float4 xv = *(const float4*)(xT + c*36 + p0);
        float4 wv = *(const float4*)(Wt + c*68 + o0);
        float2 x01 = make_float2(xv.x, xv.y);
        float2 x23 = make_float2(xv.z, xv.w);
        float2 w0 = make_float2(wv.x, wv.x);
        float2 w1 = make_float2(wv.y, wv.y);
        float2 w2 = make_float2(wv.z, wv.z);
        float2 w3 = make_float2(wv.w, wv.w);
        fma2(acc[0][0], x01, w0);
        fma2(acc[0][1], x01, w1);
        fma2(acc[0][2], x01, w2);
        fma2(acc[0][3], x01, w3);
        fma2(acc[1][0], x23, w0);
        fma2(acc[1][1], x23, w1);
        fma2(acc[1][2], x23, w2);
        fma2(acc[1][3], x23, w3);
    }
    #pragma unroll
    for (int oi = 0; oi < 4; oi++) {
        y[0][oi] = acc[0][oi].x;
        y[1][oi] = acc[0][oi].y;
        y[2][oi] = acc[1][oi].x;
        y[3][oi] = acc[1][oi].y;
    }
    #pragma unroll
    for (int pi = 0; pi < 4; pi++) {
        float s  = y[pi][0] + y[pi][1] + y[pi][2] + y[pi][3];
        float ss = y[pi][0]*y[pi][0] + y[pi][1]*y[pi][1]
                 + y[pi][2]*y[pi][2] + y[pi][3]*y[pi][3];
        #pragma unroll
        for (int off = 8; off >= 1; off >>= 1) {
            s  += __shfl_xor_sync(0xffffffffu, s,  off);
            ss += __shfl_xor_sync(0xffffffffu, ss, off);
        }
        float m = s * (1.f/64.f);
        float r = rsqrtf(ss * (1.f/64.f) - m*m + 1e-5f);
        #pragma unroll
        for (int oi = 0; oi < 4; oi++) {
            float t = (y[pi][oi] - m) * r * gb[o0+oi] + gb[64+o0+oi];
            y[pi][oi] = mishf(t);
        }
    }
}

__global__ void __launch_bounds__(128, 3) vfe_kernel(
    const float* __restrict__ voxels, const float* __restrict__ voxelmask,
    const float* __restrict__ W1, const float* __restrict__ g1, const float* __restrict__ b1,
    const float* __restrict__ W2, const float* __restrict__ g2, const float* __restrict__ b2,
    const float* __restrict__ W3, const float* __restrict__ g3, const float* __restrict__ b3,
    const float* __restrict__ W4, const float* __restrict__ g4, const float* __restrict__ b4)
{
    float* sW1t = sm_dyn + A_W1T;
    float* sW2t = sm_dyn + A_W2T;
    float* sW3t = sm_dyn + A_W3T;
    float* sW4t = sm_dyn + A_W4T;
    float* sGB  = sm_dyn + A_GB;
    float* sXTA = sm_dyn + A_XT;
    float* sXTB = sm_dyn + A_XT + 2304;
    float* sMsk = sm_dyn + A_MSK;

    const int tid = threadIdx.x;

    for (int i = tid; i < 64*CIN; i += 128) {
        int o = i / CIN, c = i - o*CIN;
        sW1t[c*68 + o] = W1[i];
    }
    for (int i = tid; i < 64*64; i += 128) {
        int o = i >> 6, c = i & 63;
        sW2t[c*68 + o] = W2[i];
        sW3t[c*68 + o] = W3[i];
        sW4t[c*68 + o] = W4[i];
    }
    if (tid < 64) {
        sGB[      tid] = g1[tid];  sGB[ 64 + tid] = b1[tid];
        sGB[128 + tid] = g2[tid];  sGB[192 + tid] = b2[tid];
        sGB[256 + tid] = g3[tid];  sGB[320 + tid] = b3[tid];
        sGB[384 + tid] = g4[tid];  sGB[448 + tid] = b4[tid];
    }

    const int pgrp = tid >> 4, ogrp = tid & 15;
    const int p0 = pgrp * 4,  o0 = ogrp * 4;

    for (int vb = 0; vb < VPB; vb++) {
        const int vA = (blockIdx.x * VPB + vb) * 2;
        const int vB = vA + 1;
        __syncthreads();
        for (int i = tid; i < PPV*CIN; i += 128) {
            int p = i / CIN, c = i - p*CIN;
            sXTA[c*36 + p] = voxels[vA * (PPV*CIN) + i];
            sXTB[c*36 + p] = voxels[vB * (PPV*CIN) + i];
        }
        if (tid < 2*PPV) {
            int which = tid >> 5, pp = tid & 31;
            sMsk[tid] = voxelmask[(vA + which)*PPV + pp];
        }
        __syncthreads();

        float mskA[4], mskB[4];
        #pragma unroll
        for (int pi = 0; pi < 4; pi++) {
            mskA[pi] = sMsk[p0 + pi];
            mskB[pi] = sMsk[32 + p0 + pi];
        }

        float yA[4][4], yB[4][4], x2rA[4][4], x2rB[4][4];

        fel_layer<CIN>(sW1t, sGB, sXTA, p0, o0, yA);
        fel_layer<CIN>(sW1t, sGB, sXTB, p0, o0, yB);
        __syncthreads();
        #pragma unroll
        for (int oi = 0; oi < 4; oi++) {
            *(float4*)(sXTA + (o0+oi)*36 + p0) =
                make_float4(yA[0][oi], yA[1][oi], yA[2][oi], yA[3][oi]);
            *(float4*)(sXTB + (o0+oi)*36 + p0) =
                make_float4(yB[0][oi], yB[1][oi], yB[2][oi], yB[3][oi]);
        }
        __syncthreads();

        fel_layer<64>(sW2t, sGB + 128, sXTA, p0, o0, yA);
        fel_layer<64>(sW2t, sGB + 128, sXTB, p0, o0, yB);
        #pragma unroll
        for (int pi = 0; pi < 4; pi++)
            #pragma unroll
            for (int oi = 0; oi < 4; oi++) {
                yA[pi][oi] *= mskA[pi];  x2rA[pi][oi] = yA[pi][oi];
                yB[pi][oi] *= mskB[pi];  x2rB[pi][oi] = yB[pi][oi];
            }
        __syncthreads();
        #pragma unroll
        for (int oi = 0; oi < 4; oi++) {
            *(float4*)(sXTA + (o0+oi)*36 + p0) =
                make_float4(yA[0][oi], yA[1][oi], yA[2][oi], yA[3][oi]);
            *(float4*)(sXTB + (o0+oi)*36 + p0) =
                make_float4(yB[0][oi], yB[1][oi], yB[2][oi], yB[3][oi]);
        }
        __syncthreads();

        fel_layer<64>(sW3t, sGB + 256, sXTA, p0, o0, yA);
        fel_layer<64>(sW3t, sGB + 256, sXTB, p0, o0, yB);
        __syncthreads();
        #pragma unroll
        for (int oi = 0; oi < 4; oi++) {
            *(float4*)(sXTA + (o0+oi)*36 + p0) =
                make_float4(yA[0][oi], yA[1][oi], yA[2][oi], yA[3][oi]);
            *(float4*)(sXTB + (o0+oi)*36 + p0) =
                make_float4(yB[0][oi], yB[1][oi], yB[2][oi], yB[3][oi]);
        }
        __syncthreads();

        fel_layer<64>(sW4t, sGB + 384, sXTA, p0, o0, yA);
        fel_layer<64>(sW4t, sGB + 384, sXTB, p0, o0, yB);
        float mxA[4], mxB[4];
        #pragma unroll
        for (int oi = 0; oi < 4; oi++) {
            #pragma unroll
            for (int pi = 0; pi < 4; pi++) {
                yA[pi][oi] = fmaf(yA[pi][oi], mskA[pi], x2rA[pi][oi]);
                yB[pi][oi] = fmaf(yB[pi][oi], mskB[pi], x2rB[pi][oi]);
            }
            mxA[oi] = fmaxf(fmaxf(yA[0][oi], yA[1][oi]), fmaxf(yA[2][oi], yA[3][oi]));
            mxB[oi] = fmaxf(fmaxf(yB[0][oi], yB[1][oi]), fmaxf(yB[2][oi], yB[3][oi]));
        }
        __syncthreads();
        #pragma unroll
        for (int oi = 0; oi < 4; oi++) {
            sXTA[(o0+oi)*36 + pgrp] = mxA[oi];
            sXTB[(o0+oi)*36 + pgrp] = mxB[oi];
        }
        __syncthreads();
        if (tid < 64) {
            float mA = sXTA[tid*36], mB = sXTB[tid*36];
            #pragma unroll
            for (int j = 1; j < 8; j++) {
                mA = fmaxf(mA, sXTA[tid*36 + j]);
                mB = fmaxf(mB, sXTB[tid*36 + j]);
            }
            g_voxelwise[vA*64 + tid] = mA;
            g_voxelwise[vB*64 + tid] = mB;
        }
    }
}

// ============================================================================
// Kernel 2 (REBUILT GATHER): bfe1 + bevmask + bfe2a, o-quarter split compute
// (unchanged) + COALESCED float4 gather staged to p-major smem.
// grid=(125,16). block=128 = 8 quads(4 cells) x 4p x 4h. Dynamic smem 52.9KB.
// ============================================================================
#define B1_W1T 0        // [64][68] = 4352
#define B1_W2A 4352     // [8][64]  = 512
#define B1_G1  4864
#define B1_B1  4928
#define B1_G2A 4992
#define B1_B2A 5000
#define B1_MSK 5008     // 32
#define B1_XP  5040     // [4p][32 cells][64 v] = 8192
#define B1_SMEM_FLOATS 13232
#define B1_SMEM_BYTES  (B1_SMEM_FLOATS * 4)

__global__ void __launch_bounds__(128, 4) bev1_kernel(
    const int*   __restrict__ bevsidx, const float* __restrict__ bevmask,
    const float* __restrict__ W1,  const float* __restrict__ G1,  const float* __restrict__ Bb1,
    const float* __restrict__ W2a, const float* __restrict__ G2a, const float* __restrict__ B2a)
{
    float* sW1t = sm_dyn + B1_W1T;
    float* sW2a = sm_dyn + B1_W2A;
    float* sG1  = sm_dyn + B1_G1;
    float* sB1  = sm_dyn + B1_B1;
    float* sG2a = sm_dyn + B1_G2A;
    float* sB2a = sm_dyn + B1_B2A;
    float* smask= sm_dyn + B1_MSK;
    float* sXp  = sm_dyn + B1_XP;    // [p][cell][v]

    const int tid = threadIdx.x;
    const int g = blockIdx.y;

    for (int i = tid; i < 4096; i += 128) {
        int o = i >> 6, v = i & 63;
        sW1t[v*68 + o] = W1[g*4096 + i];
    }
    for (int i = tid; i < 512; i += 128) sW2a[i] = W2a[g*512 + i];
    if (tid < 64) { sG1[tid] = G1[g*64 + tid]; sB1[tid] = Bb1[g*64 + tid]; }
    if (tid < 8)  { sG2a[tid] = G2a[g*8 + tid]; sB2a[tid] = B2a[g*8 + tid]; }

    const int h    = tid & 3;
    const int p    = (tid >> 2) & 3;
    const int quad = tid >> 4;
    const int obase = h*16;

    for (int n0 = blockIdx.x * 32; n0 < NB; n0 += gridDim.x * 32) {
        __syncthreads();   // protect sXp reuse
        // coalesced gather: one float4 per (cell,v), scattered p-major to smem
        #pragma unroll 4
        for (int i = tid; i < 2048; i += 128) {
            int idx = bevsidx[n0*64 + i];
            float4 xv = *(const float4*)(g_voxelwise + idx*64 + g*4);
            sXp[          i] = xv.x;
            sXp[2048 +    i] = xv.y;
            sXp[4096 +    i] = xv.z;
            sXp[6144 +    i] = xv.w;
        }
        if (tid < 32) smask[tid] = bevmask[n0 + tid];
        __syncthreads();

        const int cell0 = quad * 4;
        const float* xrow = sXp + p*2048 + cell0*64;

        float2 acc[4][8];
        #pragma unroll
        for (int k = 0; k < 4; k++)
            #pragma unroll
            for (int j = 0; j < 8; j++) acc[k][j] = make_float2(0.f, 0.f);

        for (int v0 = 0; v0 < 64; v0 += 4) {
            float4 xq0 = *(const float4*)(xrow + v0);
            float4 xq1 = *(const float4*)(xrow + 64 + v0);
            float4 xq2 = *(const float4*)(xrow + 128 + v0);
            float4 xq3 = *(const float4*)(xrow + 192 + v0);

            #define B1STEP(DV, COMP)                                          \
            {                                                                 \
                const float* wr = sW1t + (v0+DV)*68 + obase;                  \
                float4 w0 = *(const float4*)(wr);                             \
                float4 w1 = *(const float4*)(wr + 4);                         \
                float4 w2 = *(const float4*)(wr + 8);                         \
                float4 w3 = *(const float4*)(wr + 12);                        \
                float2 wp0 = make_float2(w0.x, w0.y), wp1 = make_float2(w0.z, w0.w); \
                float2 wp2 = make_float2(w1.x, w1.y), wp3 = make_float2(w1.z, w1.w); \
                float2 wp4 = make_float2(w2.x, w2.y), wp5 = make_float2(w2.z, w2.w); \
                float2 wp6 = make_float2(w3.x, w3.y), wp7 = make_float2(w3.z, w3.w); \
                float2 xb;                                                    \
                xb = make_float2(xq0.COMP, xq0.COMP);                         \
                fma2(acc[0][0], xb, wp0); fma2(acc[0][1], xb, wp1);           \
                fma2(acc[0][2], xb, wp2); fma2(acc[0][3], xb, wp3);           \
                fma2(acc[0][4], xb, wp4); fma2(acc[0][5], xb, wp5);           \
                fma2(acc[0][6], xb, wp6); fma2(acc[0][7], xb, wp7);           \
                xb = make_float2(xq1.COMP, xq1.COMP);                         \
                fma2(acc[1][0], xb, wp0); fma2(acc[1][1], xb, wp1);           \
                fma2(acc[1][2], xb, wp2); fma2(acc[1][3], xb, wp3);           \
                fma2(acc[1][4], xb, wp4); fma2(acc[1][5], xb, wp5);           \
                fma2(acc[1][6], xb, wp6); fma2(acc[1][7], xb, wp7);           \
                xb = make_float2(xq2.COMP, xq2.COMP);                         \
                fma2(acc[2][0], xb, wp0); fma2(acc[2][1], xb, wp1);           \
                fma2(acc[2][2], xb, wp2); fma2(acc[2][3], xb, wp3);           \
                fma2(acc[2][4], xb, wp4); fma2(acc[2][5], xb, wp5);           \
                fma2(acc[2][6], xb, wp6); fma2(acc[2][7], xb, wp7);           \
                xb = make_float2(xq3.COMP, xq3.COMP);                         \
                fma2(acc[3][0], xb, wp0); fma2(acc[3][1], xb, wp1);           \
                fma2(acc[3][2], xb, wp2); fma2(acc[3][3], xb, wp3);           \
                fma2(acc[3][4], xb, wp4); fma2(acc[3][5], xb, wp5);           \
                fma2(acc[3][6], xb, wp6); fma2(acc[3][7], xb, wp7);           \
            }
            B1STEP(0, x)
            B1STEP(1, y)
            B1STEP(2, z)
            B1STEP(3, w)
            #undef B1STEP
        }

        // ---- LN(64) per (cell,p): combine across 4 h-lanes ----
        float m[4], r[4], mk[4];
        #pragma unroll
        for (int k = 0; k < 4; k++) {
            float s = 0.f, ss = 0.f;
            #pragma unroll
            for (int j = 0; j < 8; j++) {
                s  += acc[k][j].x + acc[k][j].y;
                ss += acc[k][j].x*acc[k][j].x + acc[k][j].y*acc[k][j].y;
            }
            s  += __shfl_xor_sync(0xffffffffu, s,  1);
            ss += __shfl_xor_sync(0xffffffffu, ss, 1);
            s  += __shfl_xor_sync(0xffffffffu, s,  2);
            ss += __shfl_xor_sync(0xffffffffu, ss, 2);
            m[k] = s * (1.f/64.f);
            r[k] = rsqrtf(ss * (1.f/64.f) - m[k]*m[k] + 1e-5f);
            mk[k] = smask[cell0 + k];
        }

        #pragma unroll
        for (int k = 0; k < 4; k++) {
            #pragma unroll
            for (int j = 0; j < 8; j++) {
                int cc = obase + 2*j;
                acc[k][j].x = mishf((acc[k][j].x - m[k])*r[k]*sG1[cc  ] + sB1[cc  ]) * mk[k];
                acc[k][j].y = mishf((acc[k][j].y - m[k])*r[k]*sG1[cc+1] + sB1[cc+1]) * mk[k];
            }
        }

        // ---- bfe2a: per-o8 partials from my c-quarter + LN(8) on the fly ----
        float zm[4][2];
        float s2[4], q2[4];
        #pragma unroll
        for (int k = 0; k < 4; k++) { s2[k] = 0.f; q2[k] = 0.f; }

        #pragma unroll
        for (int o8 = 0; o8 < 8; o8++) {
            const float* wr2 = sW2a + o8*64 + obase;
            float4 u0 = *(const float4*)(wr2);
            float4 u1 = *(const float4*)(wr2 + 4);
            float4 u2 = *(const float4*)(wr2 + 8);
            float4 u3 = *(const float4*)(wr2 + 12);
            float2 vp0 = make_float2(u0.x, u0.y), vp1 = make_float2(u0.z, u0.w);
            float2 vp2 = make_float2(u1.x, u1.y), vp3 = make_float2(u1.z, u1.w);
            float2 vp4 = make_float2(u2.x, u2.y), vp5 = make_float2(u2.z, u2.w);
            float2 vp6 = make_float2(u3.x, u3.y), vp7 = make_float2(u3.z, u3.w);
            #pragma unroll
            for (int k = 0; k < 4; k++) {
                float2 a = make_float2(0.f, 0.f);
                fma2(a, acc[k][0], vp0); fma2(a, acc[k][1], vp1);
                fma2(a, acc[k][2], vp2); fma2(a, acc[k][3], vp3);
                fma2(a, acc[k][4], vp4); fma2(a, acc[k][5], vp5);
                fma2(a, acc[k][6], vp6); fma2(a, acc[k][7], vp7);
                float t = a.x + a.y;
                t += __shfl_xor_sync(0xffffffffu, t, 1);
                t += __shfl_xor_sync(0xffffffffu, t, 2);
                s2[k] += t; q2[k] += t*t;
                if ((o8 >> 1) == h) zm[k][o8 & 1] = t;
            }
        }

        #pragma unroll
        for (int k = 0; k < 4; k++) {
            float m2 = s2[k] * 0.125f;
            float r2 = rsqrtf(q2[k] * 0.125f - m2*m2 + 1e-5f);
            float* dst = g_h2 + (n0 + cell0 + k)*512 + g*32 + p*8;
            int oA = h*2, oB = h*2 + 1;
            dst[oA] = mishf((zm[k][0] - m2) * r2 * sG2a[oA] + sB2a[oA]);
            dst[oB] = mishf((zm[k][1] - m2) * r2 * sG2a[oB] + sB2a[oB]);
        }
    }
}

// ============================================================================
// Kernel 3: bfe2b + bfe3(x2) + residual + scatter (R7 version, ~144us).
// ============================================================================
#define B2_SMEM_FLOATS 28224
#define B2_SMEM_BYTES  (B2_SMEM_FLOATS * 4)

__device__ __forceinline__ void block_ln4(
    const float z[4], float* sred, int lane, int warp4, int bar,
    float m[4], float r[4])
{
    float s[4], q[4];
    #pragma unroll
    for (int k = 0; k < 4; k++) { s[k] = z[k]; q[k] = z[k]*z[k]; }
    #pragma unroll
    for (int off = 16; off >= 1; off >>= 1) {
        #pragma unroll
        for (int k = 0; k < 4; k++) {
            s[k] += __shfl_xor_sync(0xffffffffu, s[k], off);
            q[k] += __shfl_xor_sync(0xffffffffu, q[k], off);
        }
    }
    if (lane == 0) {
        #pragma unroll
        for (int k = 0; k < 4; k++) {
            sred[warp4*8 + k]     = s[k];
            sred[warp4*8 + 4 + k] = q[k];
        }
    }
    barg(bar);
    #pragma unroll
    for (int k = 0; k < 4; k++) {
        s[k] = sred[k]   + sred[8+k]  + sred[16+k] + sred[24+k];
        q[k] = sred[4+k] + sred[12+k] + sred[20+k] + sred[28+k];
    }
    barg(bar);
    #pragma unroll
    for (int k = 0; k < 4; k++) {
        m[k] = s[k] * (1.f/128.f);
        r[k] = rsqrtf(q[k] * (1.f/128.f) - m[k]*m[k] + 1e-5f);
    }
}

__global__ void __launch_bounds__(256) bev2_kernel(
    const float* __restrict__ W2b, const float* __restrict__ G2b, const float* __restrict__ B2b,
    const float* __restrict__ W3,  const float* __restrict__ G3,  const float* __restrict__ B3,
    const int*   __restrict__ bevcoors,
    float* __restrict__ out)
{
    const int tid = threadIdx.x;
    const int q = tid >> 7;
    const int t = tid & 127;
    const int bar = q + 1;
    const int lane = t & 31, warp4 = t >> 5;
    const int g = t >> 3;

    float* sW2b = sm_dyn;                     // 128 x 36
    float* sW3  = sm_dyn + 4608;              // 128 x 132
    float* sG2b = sm_dyn + 21504;
    float* sB2b = sm_dyn + 21632;
    float* sG3  = sm_dyn + 21760;
    float* sB3  = sm_dyn + 21888;
    float* sH   = sm_dyn + 22016 + q*2048;
    float* s17  = sm_dyn + 26112 + q*512;
    float* s18  = sm_dyn + 27136 + q*512;
    float* sred = sm_dyn + 28160 + q*32;

    for (int i = tid; i < 128*32; i += 256) {
        int o = i >> 5, c = i & 31;
        sW2b[o*36 + c] = W2b[i];
    }
    for (int i = tid; i < 128*128; i += 256) {
        int o = i >> 7, c = i & 127;
        sW3[o*132 + c] = W3[i];
    }
    if (tid < 128) {
        sG2b[tid] = G2b[tid]; sB2b[tid] = B2b[tid];
        sG3[tid]  = G3[tid];  sB3[tid]  = B3[tid];
    }
    __syncthreads();

    for (int qb = blockIdx.x; qb < NB/8; qb += gridDim.x) {
        const int n0 = qb*8 + q*4;
        barg(bar);
        for (int i = t; i < 2048; i += 128)
            sH[i] = g_h2[n0*512 + i];
        barg(bar);

        float2 a0 = {0.f,0.f}, a1 = {0.f,0.f}, a2 = {0.f,0.f}, a3 = {0.f,0.f};
        {
            const float* wr = sW2b + t*36;
            const float* h0 = sH + g*32;
            #pragma unroll
            for (int c = 0; c < 32; c += 4) {
                float4 w  = *(const float4*)(wr + c);
                float2 wlo = make_float2(w.x, w.y), whi = make_float2(w.z, w.w);
                float4 xa = *(const float4*)(h0 + c);
                float4 xb = *(const float4*)(h0 + 512 + c);
                float4 xc = *(const float4*)(h0 + 1024 + c);
                float4 xd = *(const float4*)(h0 + 1536 + c);
                fma2(a0, make_float2(xa.x, xa.y), wlo);
                fma2(a0, make_float2(xa.z, xa.w), whi);
                fma2(a1, make_float2(xb.x, xb.y), wlo);
                fma2(a1, make_float2(xb.z, xb.w), whi);
                fma2(a2, make_float2(xc.x, xc.y), wlo);
                fma2(a2, make_float2(xc.z, xc.w), whi);
                fma2(a3, make_float2(xd.x, xd.y), wlo);
                fma2(a3, make_float2(xd.z, xd.w), whi);
            }
        }
        float zz[4] = { a0.x + a0.y, a1.x + a1.y, a2.x + a2.y, a3.x + a3.y };

        float x17[4];
        {
            float s[4], qq[4];
            #pragma unroll
            for (int k = 0; k < 4; k++) { s[k] = zz[k]; qq[k] = zz[k]*zz[k]; }
            #pragma unroll
            for (int off = 4; off >= 1; off >>= 1) {
                #pragma unroll
                for (int k = 0; k < 4; k++) {
                    s[k]  += __shfl_xor_sync(0xffffffffu, s[k],  off);
                    qq[k] += __shfl_xor_sync(0xffffffffu, qq[k], off);
                }
            }
            #pragma unroll
            for (int k = 0; k < 4; k++) {
                float mm = s[k] * 0.125f;
                float rr = rsqrtf(qq[k] * 0.125f - mm*mm + 1e-5f);
                x17[k] = mishf((zz[k] - mm) * rr * sG2b[t] + sB2b[t]);
                s17[k*128 + t] = x17[k];
            }
        }
        barg(bar);

        const float* wr3 = sW3 + t*132;

        a0 = make_float2(0.f,0.f); a1 = make_float2(0.f,0.f);
        a2 = make_float2(0.f,0.f); a3 = make_float2(0.f,0.f);
        #pragma unroll 8
        for (int c = 0; c < 128; c += 4) {
            float4 w  = *(const float4*)(wr3 + c);
            float2 wlo = make_float2(w.x, w.y), whi = make_float2(w.z, w.w);
            float4 xa = *(const float4*)(s17 + c);
            float4 xb = *(const float4*)(s17 + 128 + c);
            float4 xc = *(const float4*)(s17 + 256 + c);
            float4 xd = *(const float4*)(s17 + 384 + c);
            fma2(a0, make_float2(xa.x, xa.y), wlo);
            fma2(a0, make_float2(xa.z, xa.w), whi);
            fma2(a1, make_float2(xb.x, xb.y), wlo);
            fma2(a1, make_float2(xb.z, xb.w), whi);
            fma2(a2, make_float2(xc.x, xc.y), wlo);
            fma2(a2, make_float2(xc.z, xc.w), whi);
            fma2(a3, make_float2(xd.x, xd.y), wlo);
            fma2(a3, make_float2(xd.z, xd.w), whi);
        }
        zz[0] = a0.x + a0.y; zz[1] = a1.x + a1.y;
        zz[2] = a2.x + a2.y; zz[3] = a3.x + a3.y;
        {
            float m[4], r[4];
            block_ln4(zz, sred, lane, warp4, bar, m, r);
            #pragma unroll
            for (int k = 0; k < 4; k++)
                s18[k*128 + t] = mishf((zz[k] - m[k]) * r[k] * sG3[t] + sB3[t]);
        }
        barg(bar);

        a0 = make_float2(0.f,0.f); a1 = make_float2(0.f,0.f);
        a2 = make_float2(0.f,0.f); a3 = make_float2(0.f,0.f);
        #pragma unroll 8
        for (int c = 0; c < 128; c += 4) {
            float4 w  = *(const float4*)(wr3 + c);
            float2 wlo = make_float2(w.x, w.y), whi = make_float2(w.z, w.w);
            float4 xa = *(const float4*)(s18 + c);
            float4 xb = *(const float4*)(s18 + 128 + c);
            float4 xc = *(const float4*)(s18 + 256 + c);
            float4 xd = *(const float4*)(s18 + 384 + c);
            fma2(a0, make_float2(xa.x, xa.y), wlo);
            fma2(a0, make_float2(xa.z, xa.w), whi);
            fma2(a1, make_float2(xb.x, xb.y), wlo);
            fma2(a1, make_float2(xb.z, xb.w), whi);
            fma2(a2, make_float2(xc.x, xc.y), wlo);
            fma2(a2, make_float2(xc.z, xc.w), whi);
            fma2(a3, make_float2(xd.x, xd.y), wlo);
            fma2(a3, make_float2(xd.z, xd.w), whi);
        }
        zz[0] = a0.x + a0.y; zz[1] = a1.x + a1.y;
        zz[2] = a2.x + a2.y; zz[3] = a3.x + a3.y;
        {
            float m[4], r[4];
            block_ln4(zz, sred, lane, warp4, bar, m, r);
            #pragma unroll
            for (int k = 0; k < 4; k++) {
                float x19 = mishf((zz[k] - m[k]) * r[k] * sG3[t] + sB3[t]) + x17[k];
                int2 cc = ((const int2*)bevcoors)[n0 + k];
                out[t*OUTWH + cc.y*BH + cc.x] = x19;
            }
        }
    }
}

// ============================================================================
// launch
// ============================================================================
extern "C" void kernel_launch(void* const* d_in, const int* in_sizes, int n_in,
                              void* d_out, int out_size)
{
    (void)in_sizes; (void)n_in; (void)out_size;

    const float* voxels    = (const float*)d_in[0];
    const float* voxelmask = (const float*)d_in[1];
    const int*   bevsidx   = (const int*)d_in[2];
    const int*   bevcoors  = (const int*)d_in[3];
    const float* bevmask   = (const float*)d_in[4];
    float* out = (float*)d_out;

    cudaFuncSetAttribute(vfe_kernel,  cudaFuncAttributeMaxDynamicSharedMemorySize, A_SMEM_BYTES);
    cudaFuncSetAttribute(bev1_kernel, cudaFuncAttributeMaxDynamicSharedMemorySize, B1_SMEM_BYTES);
    cudaFuncSetAttribute(bev2_kernel, cudaFuncAttributeMaxDynamicSharedMemorySize, B2_SMEM_BYTES);

    zero_kernel<<<(OUTSZ/4 + 255)/256, 256>>>((float4*)out, OUTSZ/4);

    vfe_kernel<<<NV/(2*VPB), 128, A_SMEM_BYTES>>>(
        voxels, voxelmask,
        (const float*)d_in[5],  (const float*)d_in[6],  (const float*)d_in[7],
        (const float*)d_in[8],  (const float*)d_in[9],  (const float*)d_in[10],
        (const float*)d_in[11], (const float*)d_in[12], (const float*)d_in[13],
        (const float*)d_in[14], (const float*)d_in[15], (const float*)d_in[16]);

    bev1_kernel<<<dim3(125, 16), 128, B1_SMEM_BYTES>>>(
        bevsidx, bevmask,
        (const float*)d_in[17], (const float*)d_in[18], (const float*)d_in[19],
        (const float*)d_in[20], (const float*)d_in[21], (const float*)d_in[22]);

    bev2_kernel<<<1000, 256, B2_SMEM_BYTES>>>(
        (const float*)d_in[23], (const float*)d_in[24], (const float*)d_in[25],
        (const float*)d_in[26], (const float*)d_in[27], (const float*)d_in[28],
        bevcoors, out);
}

// round 14
// speedup vs baseline: 1.0350x; 1.0350x over previous
#include <cuda_runtime.h>

#define NV   16000
#define PPV  32
#define CIN  10
#define NB   16000
#define BH   496
#define BW   432
#define OUTWH (BW*BH)          // 214272
#define OUTSZ (128*OUTWH)      // 27426816

// ---------------- static device scratch (no runtime allocation) ----------------
__device__ __align__(16) float g_voxelwise[NV * 64];   // [Nv][64]
__device__ __align__(16) float g_h2[NB * 512];         // [Nb][16][32]

extern __shared__ float sm_dyn[];

// mish(x) = x * tanh(softplus(x)) = x * t(t+2)/(t(t+2)+2), t = e^x
__device__ __forceinline__ float mishf(float x) {
    float t = __expf(fminf(x, 20.0f));
    float r = t * (t + 2.0f);
    return x * __fdividef(r, r + 2.0f);
}

// packed f32x2 FMA: d = a*b + d (elementwise, rn) — sm_100+ FFMA2
__device__ __forceinline__ void fma2(float2& d, const float2 a, const float2 b) {
    asm("fma.rn.f32x2 %0, %1, %2, %0;"
        : "+l"(reinterpret_cast<unsigned long long&>(d))
        : "l"(reinterpret_cast<const unsigned long long&>(a)),
          "l"(reinterpret_cast<const unsigned long long&>(b)));
}

// named barrier over 128 threads (4 contiguous warps)
__device__ __forceinline__ void barg(int id) {
    asm volatile("bar.sync %0, 128;" :: "r"(id) : "memory");
}

// ============================================================================
// Kernel 0: zero the output map
// ============================================================================
__global__ void zero_kernel(float4* __restrict__ out, int n4) {
    int i = blockIdx.x * blockDim.x + threadIdx.x;
    if (i < n4) out[i] = make_float4(0.f, 0.f, 0.f, 0.f);
}

// ============================================================================
// Kernel 1: VFE — 256 threads = 2 independent voxel lanes x 128 threads.
// Lane thread = (pgrp:4 points, ogrp:4 outputs). One shared weight copy,
// per-lane named barriers. 3 blocks/SM -> 24 warps/SM (2x R12).
// ============================================================================
#define VFE_IT 8          // voxels per lane per block
#define A_W1T 0           // [10][68]
#define A_W2T 680         // [64][68]
#define A_W3T 5032
#define A_W4T 9384
#define A_GB  13736       // 4 layers x (gamma64 | beta64)
#define A_XT  14248       // 2 lanes x [64][36]
#define A_MSK 18856       // 2 lanes x [32]
#define A_SMEM_FLOATS 18920
#define A_SMEM_BYTES  (A_SMEM_FLOATS * 4)

template<int CINT>
__device__ __forceinline__ void fel_layer(
    const float* __restrict__ Wt, const float* __restrict__ gb,
    const float* __restrict__ xT, int p0, int o0, float (&y)[4][4])
{
    float2 acc[2][4];
    #pragma unroll
    for (int pj = 0; pj < 2; pj++)
        #pragma unroll
        for (int oi = 0; oi < 4; oi++) acc[pj][oi] = make_float2(0.f, 0.f);

    #pragma unroll 4
    for (int c = 0; c < CINT; c++) {
        float4 xv = *(const float4*)(xT + c*36 + p0);
        float4 wv = *(const float4*)(Wt + c*68 + o0);
        float2 x01 = make_float2(xv.x, xv.y);
        float2 x23 = make_float2(xv.z, xv.w);
        float2 w0 = make_float2(wv.x, wv.x);
        float2 w1 = make_float2(wv.y, wv.y);
        float2 w2 = make_float2(wv.z, wv.z);
        float2 w3 = make_float2(wv.w, wv.w);
        fma2(acc[0][0], x01, w0);
        fma2(acc[0][1], x01, w1);
        fma2(acc[0][2], x01, w2);
        fma2(acc[0][3], x01, w3);
        fma2(acc[1][0], x23, w0);
        fma2(acc[1][1], x23, w1);
        fma2(acc[1][2], x23, w2);
        fma2(acc[1][3], x23, w3);
    }
    #pragma unroll
    for (int oi = 0; oi < 4; oi++) {
        y[0][oi] = acc[0][oi].x;
        y[1][oi] = acc[0][oi].y;
        y[2][oi] = acc[1][oi].x;
        y[3][oi] = acc[1][oi].y;
    }
    #pragma unroll
    for (int pi = 0; pi < 4; pi++) {
        float s  = y[pi][0] + y[pi][1] + y[pi][2] + y[pi][3];
        float ss = y[pi][0]*y[pi][0] + y[pi][1]*y[pi][1]
                 + y[pi][2]*y[pi][2] + y[pi][3]*y[pi][3];
        #pragma unroll
        for (int off = 8; off >= 1; off >>= 1) {
            s  += __shfl_xor_sync(0xffffffffu, s,  off);
            ss += __shfl_xor_sync(0xffffffffu, ss, off);
        }
        float m = s * (1.f/64.f);
        float r = rsqrtf(ss * (1.f/64.f) - m*m + 1e-5f);
        #pragma unroll
        for (int oi = 0; oi < 4; oi++) {
            float t = (y[pi][oi] - m) * r * gb[o0+oi] + gb[64+o0+oi];
            y[pi][oi] = mishf(t);
        }
    }
}

__global__ void __launch_bounds__(256, 3) vfe_kernel(
    const float* __restrict__ voxels, const float* __restrict__ voxelmask,
    const float* __restrict__ W1, const float* __restrict__ g1, const float* __restrict__ b1,
    const float* __restrict__ W2, const float* __restrict__ g2, const float* __restrict__ b2,
    const float* __restrict__ W3, const float* __restrict__ g3, const float* __restrict__ b3,
    const float* __restrict__ W4, const float* __restrict__ g4, const float* __restrict__ b4)
{
    float* sW1t = sm_dyn + A_W1T;
    float* sW2t = sm_dyn + A_W2T;
    float* sW3t = sm_dyn + A_W3T;
    float* sW4t = sm_dyn + A_W4T;
    float* sGB  = sm_dyn + A_GB;

    const int tid = threadIdx.x;

    for (int i = tid; i < 64*CIN; i += 256) {
        int o = i / CIN, c = i - o*CIN;
        sW1t[c*68 + o] = W1[i];
    }
    for (int i = tid; i < 64*64; i += 256) {
        int o = i >> 6, c = i & 63;
        sW2t[c*68 + o] = W2[i];
        sW3t[c*68 + o] = W3[i];
        sW4t[c*68 + o] = W4[i];
    }
    if (tid < 64) {
        sGB[      tid] = g1[tid];  sGB[ 64 + tid] = b1[tid];
        sGB[128 + tid] = g2[tid];  sGB[192 + tid] = b2[tid];
        sGB[256 + tid] = g3[tid];  sGB[320 + tid] = b3[tid];
        sGB[384 + tid] = g4[tid];  sGB[448 + tid] = b4[tid];
    }
    __syncthreads();   // weights ready for both lanes

    const int l = tid >> 7;           // voxel lane 0/1
    const int t = tid & 127;
    const int bar = l + 1;
    float* sXT  = sm_dyn + A_XT  + l*2304;
    float* sMsk = sm_dyn + A_MSK + l*32;

    const int pgrp = t >> 4, ogrp = t & 15;
    const int p0 = pgrp * 4,  o0 = ogrp * 4;

    for (int vb = 0; vb < VFE_IT; vb++) {
        const int v = (blockIdx.x*2 + l)*VFE_IT + vb;
        barg(bar);   // protect sXT reuse from previous iteration
        for (int i = t; i < PPV*CIN; i += 128) {
            int p = i / CIN, c = i - p*CIN;
            sXT[c*36 + p] = voxels[v * (PPV*CIN) + i];
        }
        if (t < PPV) sMsk[t] = voxelmask[v*PPV + t];
        barg(bar);

        float msk[4];
        #pragma unroll
        for (int pi = 0; pi < 4; pi++) msk[pi] = sMsk[p0 + pi];

        float y[4][4], x2r[4][4];

        // ---- layer 1 (10 -> 64) ----
        fel_layer<CIN>(sW1t, sGB, sXT, p0, o0, y);
        barg(bar);
        #pragma unroll
        for (int oi = 0; oi < 4; oi++)
            *(float4*)(sXT + (o0+oi)*36 + p0) =
                make_float4(y[0][oi], y[1][oi], y[2][oi], y[3][oi]);
        barg(bar);

        // ---- layer 2 (* mask, keep residual) ----
        fel_layer<64>(sW2t, sGB + 128, sXT, p0, o0, y);
        #pragma unroll
        for (int pi = 0; pi < 4; pi++)
            #pragma unroll
            for (int oi = 0; oi < 4; oi++) {
                y[pi][oi] *= msk[pi];
                x2r[pi][oi] = y[pi][oi];
            }
        barg(bar);
        #pragma unroll
        for (int oi = 0; oi < 4; oi++)
            *(float4*)(sXT + (o0+oi)*36 + p0) =
                make_float4(y[0][oi], y[1][oi], y[2][oi], y[3][oi]);
        barg(bar);

        // ---- layer 3 ----
        fel_layer<64>(sW3t, sGB + 256, sXT, p0, o0, y);
        barg(bar);
        #pragma unroll
        for (int oi = 0; oi < 4; oi++)
            *(float4*)(sXT + (o0+oi)*36 + p0) =
                make_float4(y[0][oi], y[1][oi], y[2][oi], y[3][oi]);
        barg(bar);

        // ---- layer 4 (* mask + residual), then max over points ----
        fel_layer<64>(sW4t, sGB + 384, sXT, p0, o0, y);
        float mx[4];
        #pragma unroll
        for (int oi = 0; oi < 4; oi++) {
            #pragma unroll
            for (int pi = 0; pi < 4; pi++)
                y[pi][oi] = fmaf(y[pi][oi], msk[pi], x2r[pi][oi]);
            mx[oi] = fmaxf(fmaxf(y[0][oi], y[1][oi]), fmaxf(y[2][oi], y[3][oi]));
        }
        barg(bar);
        #pragma unroll
        for (int oi = 0; oi < 4; oi++)
            sXT[(o0+oi)*36 + pgrp] = mx[oi];   // partial max scratch
        barg(bar);
        if (t < 64) {
            float m = sXT[t*36];
            #pragma unroll
            for (int j = 1; j < 8; j++) m = fmaxf(m, sXT[t*36 + j]);
            g_voxelwise[v*64 + t] = m;
        }
    }
}

// ============================================================================
// Kernel 2: bfe1 + bevmask + bfe2a (R12 quarter-split — best measured).
// grid=(125,16): blockIdx.y = branch g. block=128 = 8 quads(4 cells) x 4p x 4h.
// ============================================================================
__global__ void __launch_bounds__(128, 4) bev1_kernel(
    const int*   __restrict__ bevsidx, const float* __restrict__ bevmask,
    const float* __restrict__ W1,  const float* __restrict__ G1,  const float* __restrict__ Bb1,
    const float* __restrict__ W2a, const float* __restrict__ G2a, const float* __restrict__ B2a)
{
    __shared__ __align__(16) float sW1t[64*68];   // [v][o] transposed (pad 68)
    __shared__ __align__(16) float sW2a[512];     // [o8][c]
    __shared__ float sG1[64], sB1[64], sG2a[8], sB2a[8];
    __shared__ int   sidx[32*64];
    __shared__ float smask[32];

    const int tid = threadIdx.x;
    const int g = blockIdx.y;

    for (int i = tid; i < 4096; i += 128) {
        int o = i >> 6, v = i & 63;
        sW1t[v*68 + o] = W1[g*4096 + i];
    }
    for (int i = tid; i < 512; i += 128) sW2a[i] = W2a[g*512 + i];
    if (tid < 64) { sG1[tid] = G1[g*64 + tid]; sB1[tid] = Bb1[g*64 + tid]; }
    if (tid < 8)  { sG2a[tid] = G2a[g*8 + tid]; sB2a[tid] = B2a[g*8 + tid]; }

    const int h    = tid & 3;
    const int p    = (tid >> 2) & 3;
    const int quad = tid >> 4;
    const int c = g*4 + p;
    const int obase = h*16;

    for (int n0 = blockIdx.x * 32; n0 < NB; n0 += gridDim.x * 32) {
        __syncthreads();
        for (int i = tid; i < 2048; i += 128)
            sidx[i] = bevsidx[n0*64 + i];
        if (tid < 32) smask[tid] = bevmask[n0 + tid];
        __syncthreads();

        const int cell0 = quad * 4;
        const int* idx0 = sidx + (cell0+0)*64;
        const int* idx1 = sidx + (cell0+1)*64;
        const int* idx2 = sidx + (cell0+2)*64;
        const int* idx3 = sidx + (cell0+3)*64;

        float2 acc[4][8];
        #pragma unroll
        for (int k = 0; k < 4; k++)
            #pragma unroll
            for (int j = 0; j < 8; j++) acc[k][j] = make_float2(0.f, 0.f);

        float xc0 = g_voxelwise[idx0[0]*64 + c], xn0 = g_voxelwise[idx0[1]*64 + c];
        float xc1 = g_voxelwise[idx1[0]*64 + c], xn1 = g_voxelwise[idx1[1]*64 + c];
        float xc2 = g_voxelwise[idx2[0]*64 + c], xn2 = g_voxelwise[idx2[1]*64 + c];
        float xc3 = g_voxelwise[idx3[0]*64 + c], xn3 = g_voxelwise[idx3[1]*64 + c];

        #pragma unroll 2
        for (int v = 0; v < 64; v++) {
            const float* wr = sW1t + v*68 + obase;
            float4 w0 = *(const float4*)(wr);
            float4 w1 = *(const float4*)(wr + 4);
            float4 w2 = *(const float4*)(wr + 8);
            float4 w3 = *(const float4*)(wr + 12);
            float2 wp0 = make_float2(w0.x, w0.y), wp1 = make_float2(w0.z, w0.w);
            float2 wp2 = make_float2(w1.x, w1.y), wp3 = make_float2(w1.z, w1.w);
            float2 wp4 = make_float2(w2.x, w2.y), wp5 = make_float2(w2.z, w2.w);
            float2 wp6 = make_float2(w3.x, w3.y), wp7 = make_float2(w3.z, w3.w);

            float2 xb;
            xb = make_float2(xc0, xc0);
            fma2(acc[0][0], xb, wp0); fma2(acc[0][1], xb, wp1);
            fma2(acc[0][2], xb, wp2); fma2(acc[0][3], xb, wp3);
            fma2(acc[0][4], xb, wp4); fma2(acc[0][5], xb, wp5);
            fma2(acc[0][6], xb, wp6); fma2(acc[0][7], xb, wp7);
            xb = make_float2(xc1, xc1);
            fma2(acc[1][0], xb, wp0); fma2(acc[1][1], xb, wp1);
            fma2(acc[1][2], xb, wp2); fma2(acc[1][3], xb, wp3);
            fma2(acc[1][4], xb, wp4); fma2(acc[1][5], xb, wp5);
            fma2(acc[1][6], xb, wp6); fma2(acc[1][7], xb, wp7);
            xb = make_float2(xc2, xc2);
            fma2(acc[2][0], xb, wp0); fma2(acc[2][1], xb, wp1);
            fma2(acc[2][2], xb, wp2); fma2(acc[2][3], xb, wp3);
            fma2(acc[2][4], xb, wp4); fma2(acc[2][5], xb, wp5);
            fma2(acc[2][6], xb, wp6); fma2(acc[2][7], xb, wp7);
            xb = make_float2(xc3, xc3);
            fma2(acc[3][0], xb, wp0); fma2(acc[3][1], xb, wp1);
            fma2(acc[3][2], xb, wp2); fma2(acc[3][3], xb, wp3);
            fma2(acc[3][4], xb, wp4); fma2(acc[3][5], xb, wp5);
            fma2(acc[3][6], xb, wp6); fma2(acc[3][7], xb, wp7);

            xc0 = xn0; xc1 = xn1; xc2 = xn2; xc3 = xn3;
            if (v + 2 < 64) {
                xn0 = g_voxelwise[idx0[v+2]*64 + c];
                xn1 = g_voxelwise[idx1[v+2]*64 + c];
                xn2 = g_voxelwise[idx2[v+2]*64 + c];
                xn3 = g_voxelwise[idx3[v+2]*64 + c];
            }
        }

        float m[4], r[4], mk[4];
        #pragma unroll
        for (int k = 0; k < 4; k++) {
            float s = 0.f, ss = 0.f;
            #pragma unroll
            for (int j = 0; j < 8; j++) {
                s  += acc[k][j].x + acc[k][j].y;
                ss += acc[k][j].x*acc[k][j].x + acc[k][j].y*acc[k][j].y;
            }
            s  += __shfl_xor_sync(0xffffffffu, s,  1);
            ss += __shfl_xor_sync(0xffffffffu, ss, 1);
            s  += __shfl_xor_sync(0xffffffffu, s,  2);
            ss += __shfl_xor_sync(0xffffffffu, ss, 2);
            m[k] = s * (1.f/64.f);
            r[k] = rsqrtf(ss * (1.f/64.f) - m[k]*m[k] + 1e-5f);
            mk[k] = smask[cell0 + k];
        }

        #pragma unroll
        for (int k = 0; k < 4; k++) {
            #pragma unroll
            for (int j = 0; j < 8; j++) {
                int cc = obase + 2*j;
                acc[k][j].x = mishf((acc[k][j].x - m[k])*r[k]*sG1[cc  ] + sB1[cc  ]) * mk[k];
                acc[k][j].y = mishf((acc[k][j].y - m[k])*r[k]*sG1[cc+1] + sB1[cc+1]) * mk[k];
            }
        }

        float zm[4][2];
        float s2[4], q2[4];
        #pragma unroll
        for (int k = 0; k < 4; k++) { s2[k] = 0.f; q2[k] = 0.f; }

        #pragma unroll
        for (int o8 = 0; o8 < 8; o8++) {
            const float* wr2 = sW2a + o8*64 + obase;
            float4 u0 = *(const float4*)(wr2);
            float4 u1 = *(const float4*)(wr2 + 4);
            float4 u2 = *(const float4*)(wr2 + 8);
            float4 u3 = *(const float4*)(wr2 + 12);
            float2 vp0 = make_float2(u0.x, u0.y), vp1 = make_float2(u0.z, u0.w);
            float2 vp2 = make_float2(u1.x, u1.y), vp3 = make_float2(u1.z, u1.w);
            float2 vp4 = make_float2(u2.x, u2.y), vp5 = make_float2(u2.z, u2.w);
            float2 vp6 = make_float2(u3.x, u3.y), vp7 = make_float2(u3.z, u3.w);
            #pragma unroll
            for (int k = 0; k < 4; k++) {
                float2 a = make_float2(0.f, 0.f);
                fma2(a, acc[k][0], vp0); fma2(a, acc[k][1], vp1);
                fma2(a, acc[k][2], vp2); fma2(a, acc[k][3], vp3);
                fma2(a, acc[k][4], vp4); fma2(a, acc[k][5], vp5);
                fma2(a, acc[k][6], vp6); fma2(a, acc[k][7], vp7);
                float t = a.x + a.y;
                t += __shfl_xor_sync(0xffffffffu, t, 1);
                t += __shfl_xor_sync(0xffffffffu, t, 2);
                s2[k] += t; q2[k] += t*t;
                if ((o8 >> 1) == h) zm[k][o8 & 1] = t;
            }
        }

        #pragma unroll
        for (int k = 0; k < 4; k++) {
            float m2 = s2[k] * 0.125f;
            float r2 = rsqrtf(q2[k] * 0.125f - m2*m2 + 1e-5f);
            float* dst = g_h2 + (n0 + cell0 + k)*512 + g*32 + p*8;
            int oA = h*2, oB = h*2 + 1;
            dst[oA] = mishf((zm[k][0] - m2) * r2 * sG2a[oA] + sB2a[oA]);
            dst[oB] = mishf((zm[k][1] - m2) * r2 * sG2a[oB] + sB2a[oB]);
        }
    }
}

// ============================================================================
// Kernel 3: bfe2b + bfe3(x2) + residual + scatter (R7 version, ~144us).
// ============================================================================
#define B2_SMEM_FLOATS 28224
#define B2_SMEM_BYTES  (B2_SMEM_FLOATS * 4)

__device__ __forceinline__ void block_ln4(
    const float z[4], float* sred, int lane, int warp4, int bar,
    float m[4], float r[4])
{
    float s[4], q[4];
    #pragma unroll
    for (int k = 0; k < 4; k++) { s[k] = z[k]; q[k] = z[k]*z[k]; }
    #pragma unroll
    for (int off = 16; off >= 1; off >>= 1) {
        #pragma unroll
        for (int k = 0; k < 4; k++) {
            s[k] += __shfl_xor_sync(0xffffffffu, s[k], off);
            q[k] += __shfl_xor_sync(0xffffffffu, q[k], off);
        }
    }
    if (lane == 0) {
        #pragma unroll
        for (int k = 0; k < 4; k++) {
            sred[warp4*8 + k]     = s[k];
            sred[warp4*8 + 4 + k] = q[k];
        }
    }
    barg(bar);
    #pragma unroll
    for (int k = 0; k < 4; k++) {
        s[k] = sred[k]   + sred[8+k]  + sred[16+k] + sred[24+k];
        q[k] = sred[4+k] + sred[12+k] + sred[20+k] + sred[28+k];
    }
    barg(bar);
    #pragma unroll
    for (int k = 0; k < 4; k++) {
        m[k] = s[k] * (1.f/128.f);
        r[k] = rsqrtf(q[k] * (1.f/128.f) - m[k]*m[k] + 1e-5f);
    }
}

__global__ void __launch_bounds__(256) bev2_kernel(
    const float* __restrict__ W2b, const float* __restrict__ G2b, const float* __restrict__ B2b,
    const float* __restrict__ W3,  const float* __restrict__ G3,  const float* __restrict__ B3,
    const int*   __restrict__ bevcoors,
    float* __restrict__ out)
{
    const int tid = threadIdx.x;
    const int q = tid >> 7;
    const int t = tid & 127;
    const int bar = q + 1;
    const int lane = t & 31, warp4 = t >> 5;
    const int g = t >> 3;

    float* sW2b = sm_dyn;                     // 128 x 36
    float* sW3  = sm_dyn + 4608;              // 128 x 132
    float* sG2b = sm_dyn + 21504;
    float* sB2b = sm_dyn + 21632;
    float* sG3  = sm_dyn + 21760;
    float* sB3  = sm_dyn + 21888;
    float* sH   = sm_dyn + 22016 + q*2048;
    float* s17  = sm_dyn + 26112 + q*512;
    float* s18  = sm_dyn + 27136 + q*512;
    float* sred = sm_dyn + 28160 + q*32;

    for (int i = tid; i < 128*32; i += 256) {
        int o = i >> 5, c = i & 31;
        sW2b[o*36 + c] = W2b[i];
    }
    for (int i = tid; i < 128*128; i += 256) {
        int o = i >> 7, c = i & 127;
        sW3[o*132 + c] = W3[i];
    }
    if (tid < 128) {
        sG2b[tid] = G2b[tid]; sB2b[tid] = B2b[tid];
        sG3[tid]  = G3[tid];  sB3[tid]  = B3[tid];
    }
    __syncthreads();

    for (int qb = blockIdx.x; qb < NB/8; qb += gridDim.x) {
        const int n0 = qb*8 + q*4;
        barg(bar);
        for (int i = t; i < 2048; i += 128)
            sH[i] = g_h2[n0*512 + i];
        barg(bar);

        float2 a0 = {0.f,0.f}, a1 = {0.f,0.f}, a2 = {0.f,0.f}, a3 = {0.f,0.f};
        {
            const float* wr = sW2b + t*36;
            const float* h0 = sH + g*32;
            #pragma unroll
            for (int c = 0; c < 32; c += 4) {
                float4 w  = *(const float4*)(wr + c);
                float2 wlo = make_float2(w.x, w.y), whi = make_float2(w.z, w.w);
                float4 xa = *(const float4*)(h0 + c);
                float4 xb = *(const float4*)(h0 + 512 + c);
                float4 xc = *(const float4*)(h0 + 1024 + c);
                float4 xd = *(const float4*)(h0 + 1536 + c);
                fma2(a0, make_float2(xa.x, xa.y), wlo);
                fma2(a0, make_float2(xa.z, xa.w), whi);
                fma2(a1, make_float2(xb.x, xb.y), wlo);
                fma2(a1, make_float2(xb.z, xb.w), whi);
                fma2(a2, make_float2(xc.x, xc.y), wlo);
                fma2(a2, make_float2(xc.z, xc.w), whi);
                fma2(a3, make_float2(xd.x, xd.y), wlo);
                fma2(a3, make_float2(xd.z, xd.w), whi);
            }
        }
        float zz[4] = { a0.x + a0.y, a1.x + a1.y, a2.x + a2.y, a3.x + a3.y };

        float x17[4];
        {
            float s[4], qq[4];
            #pragma unroll
            for (int k = 0; k < 4; k++) { s[k] = zz[k]; qq[k] = zz[k]*zz[k]; }
            #pragma unroll
            for (int off = 4; off >= 1; off >>= 1) {
                #pragma unroll
                for (int k = 0; k < 4; k++) {
                    s[k]  += __shfl_xor_sync(0xffffffffu, s[k],  off);
                    qq[k] += __shfl_xor_sync(0xffffffffu, qq[k], off);
                }
            }
            #pragma unroll
            for (int k = 0; k < 4; k++) {
                float mm = s[k] * 0.125f;
                float rr = rsqrtf(qq[k] * 0.125f - mm*mm + 1e-5f);
                x17[k] = mishf((zz[k] - mm) * rr * sG2b[t] + sB2b[t]);
                s17[k*128 + t] = x17[k];
            }
        }
        barg(bar);

        const float* wr3 = sW3 + t*132;

        a0 = make_float2(0.f,0.f); a1 = make_float2(0.f,0.f);
        a2 = make_float2(0.f,0.f); a3 = make_float2(0.f,0.f);
        #pragma unroll 8
        for (int c = 0; c < 128; c += 4) {
            float4 w  = *(const float4*)(wr3 + c);
            float2 wlo = make_float2(w.x, w.y), whi = make_float2(w.z, w.w);
            float4 xa = *(const float4*)(s17 + c);
            float4 xb = *(const float4*)(s17 + 128 + c);
            float4 xc = *(const float4*)(s17 + 256 + c);
            float4 xd = *(const float4*)(s17 + 384 + c);
            fma2(a0, make_float2(xa.x, xa.y), wlo);
            fma2(a0, make_float2(xa.z, xa.w), whi);
            fma2(a1, make_float2(xb.x, xb.y), wlo);
            fma2(a1, make_float2(xb.z, xb.w), whi);
            fma2(a2, make_float2(xc.x, xc.y), wlo);
            fma2(a2, make_float2(xc.z, xc.w), whi);
            fma2(a3, make_float2(xd.x, xd.y), wlo);
            fma2(a3, make_float2(xd.z, xd.w), whi);
        }
        zz[0] = a0.x + a0.y; zz[1] = a1.x + a1.y;
        zz[2] = a2.x + a2.y; zz[3] = a3.x + a3.y;
        {
            float m[4], r[4];
            block_ln4(zz, sred, lane, warp4, bar, m, r);
            #pragma unroll
            for (int k = 0; k < 4; k++)
                s18[k*128 + t] = mishf((zz[k] - m[k]) * r[k] * sG3[t] + sB3[t]);
        }
        barg(bar);

        a0 = make_float2(0.f,0.f); a1 = make_float2(0.f,0.f);
        a2 = make_float2(0.f,0.f); a3 = make_float2(0.f,0.f);
        #pragma unroll 8
        for (int c = 0; c < 128; c += 4) {
            float4 w  = *(const float4*)(wr3 + c);
            float2 wlo = make_float2(w.x, w.y), whi = make_float2(w.z, w.w);
            float4 xa = *(const float4*)(s18 + c);
            float4 xb = *(const float4*)(s18 + 128 + c);
            float4 xc = *(const float4*)(s18 + 256 + c);
            float4 xd = *(const float4*)(s18 + 384 + c);
            fma2(a0, make_float2(xa.x, xa.y), wlo);
            fma2(a0, make_float2(xa.z, xa.w), whi);
            fma2(a1, make_float2(xb.x, xb.y), wlo);
            fma2(a1, make_float2(xb.z, xb.w), whi);
            fma2(a2, make_float2(xc.x, xc.y), wlo);
            fma2(a2, make_float2(xc.z, xc.w), whi);
            fma2(a3, make_float2(xd.x, xd.y), wlo);
            fma2(a3, make_float2(xd.z, xd.w), whi);
        }
        zz[0] = a0.x + a0.y; zz[1] = a1.x + a1.y;
        zz[2] = a2.x + a2.y; zz[3] = a3.x + a3.y;
        {
            float m[4], r[4];
            block_ln4(zz, sred, lane, warp4, bar, m, r);
            #pragma unroll
            for (int k = 0; k < 4; k++) {
                float x19 = mishf((zz[k] - m[k]) * r[k] * sG3[t] + sB3[t]) + x17[k];
                int2 cc = ((const int2*)bevcoors)[n0 + k];
                out[t*OUTWH + cc.y*BH + cc.x] = x19;
            }
        }
    }
}

// ============================================================================
// launch
// ============================================================================
extern "C" void kernel_launch(void* const* d_in, const int* in_sizes, int n_in,
                              void* d_out, int out_size)
{
    (void)in_sizes; (void)n_in; (void)out_size;

    const float* voxels    = (const float*)d_in[0];
    const float* voxelmask = (const float*)d_in[1];
    const int*   bevsidx   = (const int*)d_in[2];
    const int*   bevcoors  = (const int*)d_in[3];
    const float* bevmask   = (const float*)d_in[4];
    float* out = (float*)d_out;

    cudaFuncSetAttribute(vfe_kernel,  cudaFuncAttributeMaxDynamicSharedMemorySize, A_SMEM_BYTES);
    cudaFuncSetAttribute(bev2_kernel, cudaFuncAttributeMaxDynamicSharedMemorySize, B2_SMEM_BYTES);

    zero_kernel<<<(OUTSZ/4 + 255)/256, 256>>>((float4*)out, OUTSZ/4);

    vfe_kernel<<<NV/(2*VFE_IT), 256, A_SMEM_BYTES>>>(
        voxels, voxelmask,
        (const float*)d_in[5],  (const float*)d_in[6],  (const float*)d_in[7],
        (const float*)d_in[8],  (const float*)d_in[9],  (const float*)d_in[10],
        (const float*)d_in[11], (const float*)d_in[12], (const float*)d_in[13],
        (const float*)d_in[14], (const float*)d_in[15], (const float*)d_in[16]);

    bev1_kernel<<<dim3(125, 16), 128>>>(
        bevsidx, bevmask,
        (const float*)d_in[17], (const float*)d_in[18], (const float*)d_in[19],
        (const float*)d_in[20], (const float*)d_in[21], (const float*)d_in[22]);

    bev2_kernel<<<1000, 256, B2_SMEM_BYTES>>>(
        (const float*)d_in[23], (const float*)d_in[24], (const float*)d_in[25],
        (const float*)d_in[26], (const float*)d_in[27], (const float*)d_in[28],
        bevcoors, out);
}

// round 15
// speedup vs baseline: 1.0604x; 1.0245x over previous
#include <cuda_runtime.h>

#define NV   16000
#define PPV  32
#define CIN  10
#define NB   16000
#define BH   496
#define BW   432
#define OUTWH (BW*BH)          // 214272
#define OUTSZ (128*OUTWH)      // 27426816

// ---------------- static device scratch (no runtime allocation) ----------------
__device__ __align__(16) float g_voxelwise[NV * 64];   // [Nv][64]
__device__ __align__(16) float g_h2[NB * 512];         // [Nb][16][32]

extern __shared__ float sm_dyn[];

// mish(x) = x * tanh(softplus(x)) = x * t(t+2)/(t(t+2)+2), t = e^x
__device__ __forceinline__ float mishf(float x) {
    float t = __expf(fminf(x, 20.0f));
    float r = t * (t + 2.0f);
    return x * __fdividef(r, r + 2.0f);
}

// packed f32x2 FMA: d = a*b + d (elementwise, rn) — sm_100+ FFMA2
__device__ __forceinline__ void fma2(float2& d, const float2 a, const float2 b) {
    asm("fma.rn.f32x2 %0, %1, %2, %0;"
        : "+l"(reinterpret_cast<unsigned long long&>(d))
        : "l"(reinterpret_cast<const unsigned long long&>(a)),
          "l"(reinterpret_cast<const unsigned long long&>(b)));
}

// named barrier over 128 threads (4 contiguous warps)
__device__ __forceinline__ void barg(int id) {
    asm volatile("bar.sync %0, 128;" :: "r"(id) : "memory");
}

// ============================================================================
// Kernel 1: VFE — 256 threads = 2 independent voxel lanes x 128 threads,
// PLUS output-map zeroing folded into the prologue (stores drain under the
// compute's stall shadow; replaces the standalone zero kernel).
// ============================================================================
#define VFE_IT 8          // voxels per lane per block
#define A_W1T 0           // [10][68]
#define A_W2T 680         // [64][68]
#define A_W3T 5032
#define A_W4T 9384
#define A_GB  13736       // 4 layers x (gamma64 | beta64)
#define A_XT  14248       // 2 lanes x [64][36]
#define A_MSK 18856       // 2 lanes x [32]
#define A_SMEM_FLOATS 18920
#define A_SMEM_BYTES  (A_SMEM_FLOATS * 4)

template<int CINT>
__device__ __forceinline__ void fel_layer(
    const float* __restrict__ Wt, const float* __restrict__ gb,
    const float* __restrict__ xT, int p0, int o0, float (&y)[4][4])
{
    float2 acc[2][4];
    #pragma unroll
    for (int pj = 0; pj < 2; pj++)
        #pragma unroll
        for (int oi = 0; oi < 4; oi++) acc[pj][oi] = make_float2(0.f, 0.f);

    #pragma unroll 4
    for (int c = 0; c < CINT; c++) {
        float4 xv = *(const float4*)(xT + c*36 + p0);
        float4 wv = *(const float4*)(Wt + c*68 + o0);
        float2 x01 = make_float2(xv.x, xv.y);
        float2 x23 = make_float2(xv.z, xv.w);
        float2 w0 = make_float2(wv.x, wv.x);
        float2 w1 = make_float2(wv.y, wv.y);
        float2 w2 = make_float2(wv.z, wv.z);
        float2 w3 = make_float2(wv.w, wv.w);
        fma2(acc[0][0], x01, w0);
        fma2(acc[0][1], x01, w1);
        fma2(acc[0][2], x01, w2);
        fma2(acc[0][3], x01, w3);
        fma2(acc[1][0], x23, w0);
        fma2(acc[1][1], x23, w1);
        fma2(acc[1][2], x23, w2);
        fma2(acc[1][3], x23, w3);
    }
    #pragma unroll
    for (int oi = 0; oi < 4; oi++) {
        y[0][oi] = acc[0][oi].x;
        y[1][oi] = acc[0][oi].y;
        y[2][oi] = acc[1][oi].x;
        y[3][oi] = acc[1][oi].y;
    }
    #pragma unroll
    for (int pi = 0; pi < 4; pi++) {
        float s  = y[pi][0] + y[pi][1] + y[pi][2] + y[pi][3];
        float ss = y[pi][0]*y[pi][0] + y[pi][1]*y[pi][1]
                 + y[pi][2]*y[pi][2] + y[pi][3]*y[pi][3];
        #pragma unroll
        for (int off = 8; off >= 1; off >>= 1) {
            s  += __shfl_xor_sync(0xffffffffu, s,  off);
            ss += __shfl_xor_sync(0xffffffffu, ss, off);
        }
        float m = s * (1.f/64.f);
        float r = rsqrtf(ss * (1.f/64.f) - m*m + 1e-5f);
        #pragma unroll
        for (int oi = 0; oi < 4; oi++) {
            float t = (y[pi][oi] - m) * r * gb[o0+oi] + gb[64+o0+oi];
            y[pi][oi] = mishf(t);
        }
    }
}

__global__ void __launch_bounds__(256, 3) vfe_kernel(
    const float* __restrict__ voxels, const float* __restrict__ voxelmask,
    const float* __restrict__ W1, const float* __restrict__ g1, const float* __restrict__ b1,
    const float* __restrict__ W2, const float* __restrict__ g2, const float* __restrict__ b2,
    const float* __restrict__ W3, const float* __restrict__ g3, const float* __restrict__ b3,
    const float* __restrict__ W4, const float* __restrict__ g4, const float* __restrict__ b4,
    float4* __restrict__ outz)
{
    float* sW1t = sm_dyn + A_W1T;
    float* sW2t = sm_dyn + A_W2T;
    float* sW3t = sm_dyn + A_W3T;
    float* sW4t = sm_dyn + A_W4T;
    float* sGB  = sm_dyn + A_GB;

    const int tid = threadIdx.x;

    // ---- folded zeroing of the output map (independent, fire-and-forget) ----
    {
        const int nthreads = gridDim.x * 256;
        const int base = blockIdx.x * 256 + tid;
        const float4 z4 = make_float4(0.f, 0.f, 0.f, 0.f);
        for (int i = base; i < OUTSZ/4; i += nthreads)
            outz[i] = z4;
    }

    for (int i = tid; i < 64*CIN; i += 256) {
        int o = i / CIN, c = i - o*CIN;
        sW1t[c*68 + o] = W1[i];
    }
    for (int i = tid; i < 64*64; i += 256) {
        int o = i >> 6, c = i & 63;
        sW2t[c*68 + o] = W2[i];
        sW3t[c*68 + o] = W3[i];
        sW4t[c*68 + o] = W4[i];
    }
    if (tid < 64) {
        sGB[      tid] = g1[tid];  sGB[ 64 + tid] = b1[tid];
        sGB[128 + tid] = g2[tid];  sGB[192 + tid] = b2[tid];
        sGB[256 + tid] = g3[tid];  sGB[320 + tid] = b3[tid];
        sGB[384 + tid] = g4[tid];  sGB[448 + tid] = b4[tid];
    }
    __syncthreads();   // weights ready for both lanes

    const int l = tid >> 7;           // voxel lane 0/1
    const int t = tid & 127;
    const int bar = l + 1;
    float* sXT  = sm_dyn + A_XT  + l*2304;
    float* sMsk = sm_dyn + A_MSK + l*32;

    const int pgrp = t >> 4, ogrp = t & 15;
    const int p0 = pgrp * 4,  o0 = ogrp * 4;

    for (int vb = 0; vb < VFE_IT; vb++) {
        const int v = (blockIdx.x*2 + l)*VFE_IT + vb;
        barg(bar);   // protect sXT reuse from previous iteration
        for (int i = t; i < PPV*CIN; i += 128) {
            int p = i / CIN, c = i - p*CIN;
            sXT[c*36 + p] = voxels[v * (PPV*CIN) + i];
        }
        if (t < PPV) sMsk[t] = voxelmask[v*PPV + t];
        barg(bar);

        float msk[4];
        #pragma unroll
        for (int pi = 0; pi < 4; pi++) msk[pi] = sMsk[p0 + pi];

        float y[4][4], x2r[4][4];

        // ---- layer 1 (10 -> 64) ----
        fel_layer<CIN>(sW1t, sGB, sXT, p0, o0, y);
        barg(bar);
        #pragma unroll
        for (int oi = 0; oi < 4; oi++)
            *(float4*)(sXT + (o0+oi)*36 + p0) =
                make_float4(y[0][oi], y[1][oi], y[2][oi], y[3][oi]);
        barg(bar);

        // ---- layer 2 (* mask, keep residual) ----
        fel_layer<64>(sW2t, sGB + 128, sXT, p0, o0, y);
        #pragma unroll
        for (int pi = 0; pi < 4; pi++)
            #pragma unroll
            for (int oi = 0; oi < 4; oi++) {
                y[pi][oi] *= msk[pi];
                x2r[pi][oi] = y[pi][oi];
            }
        barg(bar);
        #pragma unroll
        for (int oi = 0; oi < 4; oi++)
            *(float4*)(sXT + (o0+oi)*36 + p0) =
                make_float4(y[0][oi], y[1][oi], y[2][oi], y[3][oi]);
        barg(bar);

        // ---- layer 3 ----
        fel_layer<64>(sW3t, sGB + 256, sXT, p0, o0, y);
        barg(bar);
        #pragma unroll
        for (int oi = 0; oi < 4; oi++)
            *(float4*)(sXT + (o0+oi)*36 + p0) =
                make_float4(y[0][oi], y[1][oi], y[2][oi], y[3][oi]);
        barg(bar);

        // ---- layer 4 (* mask + residual), then max over points ----
        fel_layer<64>(sW4t, sGB + 384, sXT, p0, o0, y);
        float mx[4];
        #pragma unroll
        for (int oi = 0; oi < 4; oi++) {
            #pragma unroll
            for (int pi = 0; pi < 4; pi++)
                y[pi][oi] = fmaf(y[pi][oi], msk[pi], x2r[pi][oi]);
            mx[oi] = fmaxf(fmaxf(y[0][oi], y[1][oi]), fmaxf(y[2][oi], y[3][oi]));
        }
        barg(bar);
        #pragma unroll
        for (int oi = 0; oi < 4; oi++)
            sXT[(o0+oi)*36 + pgrp] = mx[oi];   // partial max scratch
        barg(bar);
        if (t < 64) {
            float m = sXT[t*36];
            #pragma unroll
            for (int j = 1; j < 8; j++) m = fmaxf(m, sXT[t*36 + j]);
            g_voxelwise[v*64 + t] = m;
        }
    }
}

// ============================================================================
// Kernel 2: bfe1 + bevmask + bfe2a (R12 quarter-split — best measured).
// grid=(250,16): 2 iterations per block for finer tail balance.
// block=128 = 8 quads(4 cells) x 4p x 4h.
// ============================================================================
__global__ void __launch_bounds__(128, 4) bev1_kernel(
    const int*   __restrict__ bevsidx, const float* __restrict__ bevmask,
    const float* __restrict__ W1,  const float* __restrict__ G1,  const float* __restrict__ Bb1,
    const float* __restrict__ W2a, const float* __restrict__ G2a, const float* __restrict__ B2a)
{
    __shared__ __align__(16) float sW1t[64*68];   // [v][o] transposed (pad 68)
    __shared__ __align__(16) float sW2a[512];     // [o8][c]
    __shared__ float sG1[64], sB1[64], sG2a[8], sB2a[8];
    __shared__ int   sidx[32*64];
    __shared__ float smask[32];

    const int tid = threadIdx.x;
    const int g = blockIdx.y;

    for (int i = tid; i < 4096; i += 128) {
        int o = i >> 6, v = i & 63;
        sW1t[v*68 + o] = W1[g*4096 + i];
    }
    for (int i = tid; i < 512; i += 128) sW2a[i] = W2a[g*512 + i];
    if (tid < 64) { sG1[tid] = G1[g*64 + tid]; sB1[tid] = Bb1[g*64 + tid]; }
    if (tid < 8)  { sG2a[tid] = G2a[g*8 + tid]; sB2a[tid] = B2a[g*8 + tid]; }

    const int h    = tid & 3;
    const int p    = (tid >> 2) & 3;
    const int quad = tid >> 4;
    const int c = g*4 + p;
    const int obase = h*16;

    for (int n0 = blockIdx.x * 32; n0 < NB; n0 += gridDim.x * 32) {
        __syncthreads();
        for (int i = tid; i < 2048; i += 128)
            sidx[i] = bevsidx[n0*64 + i];
        if (tid < 32) smask[tid] = bevmask[n0 + tid];
        __syncthreads();

        const int cell0 = quad * 4;
        const int* idx0 = sidx + (cell0+0)*64;
        const int* idx1 = sidx + (cell0+1)*64;
        const int* idx2 = sidx + (cell0+2)*64;
        const int* idx3 = sidx + (cell0+3)*64;

        float2 acc[4][8];
        #pragma unroll
        for (int k = 0; k < 4; k++)
            #pragma unroll
            for (int j = 0; j < 8; j++) acc[k][j] = make_float2(0.f, 0.f);

        float xc0 = g_voxelwise[idx0[0]*64 + c], xn0 = g_voxelwise[idx0[1]*64 + c];
        float xc1 = g_voxelwise[idx1[0]*64 + c], xn1 = g_voxelwise[idx1[1]*64 + c];
        float xc2 = g_voxelwise[idx2[0]*64 + c], xn2 = g_voxelwise[idx2[1]*64 + c];
        float xc3 = g_voxelwise[idx3[0]*64 + c], xn3 = g_voxelwise[idx3[1]*64 + c];

        #pragma unroll 2
        for (int v = 0; v < 64; v++) {
            const float* wr = sW1t + v*68 + obase;
            float4 w0 = *(const float4*)(wr);
            float4 w1 = *(const float4*)(wr + 4);
            float4 w2 = *(const float4*)(wr + 8);
            float4 w3 = *(const float4*)(wr + 12);
            float2 wp0 = make_float2(w0.x, w0.y), wp1 = make_float2(w0.z, w0.w);
            float2 wp2 = make_float2(w1.x, w1.y), wp3 = make_float2(w1.z, w1.w);
            float2 wp4 = make_float2(w2.x, w2.y), wp5 = make_float2(w2.z, w2.w);
            float2 wp6 = make_float2(w3.x, w3.y), wp7 = make_float2(w3.z, w3.w);

            float2 xb;
            xb = make_float2(xc0, xc0);
            fma2(acc[0][0], xb, wp0); fma2(acc[0][1], xb, wp1);
            fma2(acc[0][2], xb, wp2); fma2(acc[0][3], xb, wp3);
            fma2(acc[0][4], xb, wp4); fma2(acc[0][5], xb, wp5);
            fma2(acc[0][6], xb, wp6); fma2(acc[0][7], xb, wp7);
            xb = make_float2(xc1, xc1);
            fma2(acc[1][0], xb, wp0); fma2(acc[1][1], xb, wp1);
            fma2(acc[1][2], xb, wp2); fma2(acc[1][3], xb, wp3);
            fma2(acc[1][4], xb, wp4); fma2(acc[1][5], xb, wp5);
            fma2(acc[1][6], xb, wp6); fma2(acc[1][7], xb, wp7);
            xb = make_float2(xc2, xc2);
            fma2(acc[2][0], xb, wp0); fma2(acc[2][1], xb, wp1);
            fma2(acc[2][2], xb, wp2); fma2(acc[2][3], xb, wp3);
            fma2(acc[2][4], xb, wp4); fma2(acc[2][5], xb, wp5);
            fma2(acc[2][6], xb, wp6); fma2(acc[2][7], xb, wp7);
            xb = make_float2(xc3, xc3);
            fma2(acc[3][0], xb, wp0); fma2(acc[3][1], xb, wp1);
            fma2(acc[3][2], xb, wp2); fma2(acc[3][3], xb, wp3);
            fma2(acc[3][4], xb, wp4); fma2(acc[3][5], xb, wp5);
            fma2(acc[3][6], xb, wp6); fma2(acc[3][7], xb, wp7);

            xc0 = xn0; xc1 = xn1; xc2 = xn2; xc3 = xn3;
            if (v + 2 < 64) {
                xn0 = g_voxelwise[idx0[v+2]*64 + c];
                xn1 = g_voxelwise[idx1[v+2]*64 + c];
                xn2 = g_voxelwise[idx2[v+2]*64 + c];
                xn3 = g_voxelwise[idx3[v+2]*64 + c];
            }
        }

        float m[4], r[4], mk[4];
        #pragma unroll
        for (int k = 0; k < 4; k++) {
            float s = 0.f, ss = 0.f;
            #pragma unroll
            for (int j = 0; j < 8; j++) {
                s  += acc[k][j].x + acc[k][j].y;
                ss += acc[k][j].x*acc[k][j].x + acc[k][j].y*acc[k][j].y;
            }
            s  += __shfl_xor_sync(0xffffffffu, s,  1);
            ss += __shfl_xor_sync(0xffffffffu, ss, 1);
            s  += __shfl_xor_sync(0xffffffffu, s,  2);
            ss += __shfl_xor_sync(0xffffffffu, ss, 2);
            m[k] = s * (1.f/64.f);
            r[k] = rsqrtf(ss * (1.f/64.f) - m[k]*m[k] + 1e-5f);
            mk[k] = smask[cell0 + k];
        }

        #pragma unroll
        for (int k = 0; k < 4; k++) {
            #pragma unroll
            for (int j = 0; j < 8; j++) {
                int cc = obase + 2*j;
                acc[k][j].x = mishf((acc[k][j].x - m[k])*r[k]*sG1[cc  ] + sB1[cc  ]) * mk[k];
                acc[k][j].y = mishf((acc[k][j].y - m[k])*r[k]*sG1[cc+1] + sB1[cc+1]) * mk[k];
            }
        }

        float zm[4][2];
        float s2[4], q2[4];
        #pragma unroll
        for (int k = 0; k < 4; k++) { s2[k] = 0.f; q2[k] = 0.f; }

        #pragma unroll
        for (int o8 = 0; o8 < 8; o8++) {
            const float* wr2 = sW2a + o8*64 + obase;
            float4 u0 = *(const float4*)(wr2);
            float4 u1 = *(const float4*)(wr2 + 4);
            float4 u2 = *(const float4*)(wr2 + 8);
            float4 u3 = *(const float4*)(wr2 + 12);
            float2 vp0 = make_float2(u0.x, u0.y), vp1 = make_float2(u0.z, u0.w);
            float2 vp2 = make_float2(u1.x, u1.y), vp3 = make_float2(u1.z, u1.w);
            float2 vp4 = make_float2(u2.x, u2.y), vp5 = make_float2(u2.z, u2.w);
            float2 vp6 = make_float2(u3.x, u3.y), vp7 = make_float2(u3.z, u3.w);
            #pragma unroll
            for (int k = 0; k < 4; k++) {
                float2 a = make_float2(0.f, 0.f);
                fma2(a, acc[k][0], vp0); fma2(a, acc[k][1], vp1);
                fma2(a, acc[k][2], vp2); fma2(a, acc[k][3], vp3);
                fma2(a, acc[k][4], vp4); fma2(a, acc[k][5], vp5);
                fma2(a, acc[k][6], vp6); fma2(a, acc[k][7], vp7);
                float t = a.x + a.y;
                t += __shfl_xor_sync(0xffffffffu, t, 1);
                t += __shfl_xor_sync(0xffffffffu, t, 2);
                s2[k] += t; q2[k] += t*t;
                if ((o8 >> 1) == h) zm[k][o8 & 1] = t;
            }
        }

        #pragma unroll
        for (int k = 0; k < 4; k++) {
            float m2 = s2[k] * 0.125f;
            float r2 = rsqrtf(q2[k] * 0.125f - m2*m2 + 1e-5f);
            float* dst = g_h2 + (n0 + cell0 + k)*512 + g*32 + p*8;
            int oA = h*2, oB = h*2 + 1;
            dst[oA] = mishf((zm[k][0] - m2) * r2 * sG2a[oA] + sB2a[oA]);
            dst[oB] = mishf((zm[k][1] - m2) * r2 * sG2a[oB] + sB2a[oB]);
        }
    }
}

// ============================================================================
// Kernel 3: bfe2b + bfe3(x2) + residual + scatter (R7 version, ~144us).
// ============================================================================
#define B2_SMEM_FLOATS 28224
#define B2_SMEM_BYTES  (B2_SMEM_FLOATS * 4)

__device__ __forceinline__ void block_ln4(
    const float z[4], float* sred, int lane, int warp4, int bar,
    float m[4], float r[4])
{
    float s[4], q[4];
    #pragma unroll
    for (int k = 0; k < 4; k++) { s[k] = z[k]; q[k] = z[k]*z[k]; }
    #pragma unroll
    for (int off = 16; off >= 1; off >>= 1) {
        #pragma unroll
        for (int k = 0; k < 4; k++) {
            s[k] += __shfl_xor_sync(0xffffffffu, s[k], off);
            q[k] += __shfl_xor_sync(0xffffffffu, q[k], off);
        }
    }
    if (lane == 0) {
        #pragma unroll
        for (int k = 0; k < 4; k++) {
            sred[warp4*8 + k]     = s[k];
            sred[warp4*8 + 4 + k] = q[k];
        }
    }
    barg(bar);
    #pragma unroll
    for (int k = 0; k < 4; k++) {
        s[k] = sred[k]   + sred[8+k]  + sred[16+k] + sred[24+k];
        q[k] = sred[4+k] + sred[12+k] + sred[20+k] + sred[28+k];
    }
    barg(bar);
    #pragma unroll
    for (int k = 0; k < 4; k++) {
        m[k] = s[k] * (1.f/128.f);
        r[k] = rsqrtf(q[k] * (1.f/128.f) - m[k]*m[k] + 1e-5f);
    }
}

__global__ void __launch_bounds__(256) bev2_kernel(
    const float* __restrict__ W2b, const float* __restrict__ G2b, const float* __restrict__ B2b,
    const float* __restrict__ W3,  const float* __restrict__ G3,  const float* __restrict__ B3,
    const int*   __restrict__ bevcoors,
    float* __restrict__ out)
{
    const int tid = threadIdx.x;
    const int q = tid >> 7;
    const int t = tid & 127;
    const int bar = q + 1;
    const int lane = t & 31, warp4 = t >> 5;
    const int g = t >> 3;

    float* sW2b = sm_dyn;                     // 128 x 36
    float* sW3  = sm_dyn + 4608;              // 128 x 132
    float* sG2b = sm_dyn + 21504;
    float* sB2b = sm_dyn + 21632;
    float* sG3  = sm_dyn + 21760;
    float* sB3  = sm_dyn + 21888;
    float* sH   = sm_dyn + 22016 + q*2048;
    float* s17  = sm_dyn + 26112 + q*512;
    float* s18  = sm_dyn + 27136 + q*512;
    float* sred = sm_dyn + 28160 + q*32;

    for (int i = tid; i < 128*32; i += 256) {
        int o = i >> 5, c = i & 31;
        sW2b[o*36 + c] = W2b[i];
    }
    for (int i = tid; i < 128*128; i += 256) {
        int o = i >> 7, c = i & 127;
        sW3[o*132 + c] = W3[i];
    }
    if (tid < 128) {
        sG2b[tid] = G2b[tid]; sB2b[tid] = B2b[tid];
        sG3[tid]  = G3[tid];  sB3[tid]  = B3[tid];
    }
    __syncthreads();

    for (int qb = blockIdx.x; qb < NB/8; qb += gridDim.x) {
        const int n0 = qb*8 + q*4;
        barg(bar);
        for (int i = t; i < 2048; i += 128)
            sH[i] = g_h2[n0*512 + i];
        barg(bar);

        float2 a0 = {0.f,0.f}, a1 = {0.f,0.f}, a2 = {0.f,0.f}, a3 = {0.f,0.f};
        {
            const float* wr = sW2b + t*36;
            const float* h0 = sH + g*32;
            #pragma unroll
            for (int c = 0; c < 32; c += 4) {
                float4 w  = *(const float4*)(wr + c);
                float2 wlo = make_float2(w.x, w.y), whi = make_float2(w.z, w.w);
                float4 xa = *(const float4*)(h0 + c);
                float4 xb = *(const float4*)(h0 + 512 + c);
                float4 xc = *(const float4*)(h0 + 1024 + c);
                float4 xd = *(const float4*)(h0 + 1536 + c);
                fma2(a0, make_float2(xa.x, xa.y), wlo);
                fma2(a0, make_float2(xa.z, xa.w), whi);
                fma2(a1, make_float2(xb.x, xb.y), wlo);
                fma2(a1, make_float2(xb.z, xb.w), whi);
                fma2(a2, make_float2(xc.x, xc.y), wlo);
                fma2(a2, make_float2(xc.z, xc.w), whi);
                fma2(a3, make_float2(xd.x, xd.y), wlo);
                fma2(a3, make_float2(xd.z, xd.w), whi);
            }
        }
        float zz[4] = { a0.x + a0.y, a1.x + a1.y, a2.x + a2.y, a3.x + a3.y };

        float x17[4];
        {
            float s[4], qq[4];
            #pragma unroll
            for (int k = 0; k < 4; k++) { s[k] = zz[k]; qq[k] = zz[k]*zz[k]; }
            #pragma unroll
            for (int off = 4; off >= 1; off >>= 1) {
                #pragma unroll
                for (int k = 0; k < 4; k++) {
                    s[k]  += __shfl_xor_sync(0xffffffffu, s[k],  off);
                    qq[k] += __shfl_xor_sync(0xffffffffu, qq[k], off);
                }
            }
            #pragma unroll
            for (int k = 0; k < 4; k++) {
                float mm = s[k] * 0.125f;
                float rr = rsqrtf(qq[k] * 0.125f - mm*mm + 1e-5f);
                x17[k] = mishf((zz[k] - mm) * rr * sG2b[t] + sB2b[t]);
                s17[k*128 + t] = x17[k];
            }
        }
        barg(bar);

        const float* wr3 = sW3 + t*132;

        a0 = make_float2(0.f,0.f); a1 = make_float2(0.f,0.f);
        a2 = make_float2(0.f,0.f); a3 = make_float2(0.f,0.f);
        #pragma unroll 8
        for (int c = 0; c < 128; c += 4) {
            float4 w  = *(const float4*)(wr3 + c);
            float2 wlo = make_float2(w.x, w.y), whi = make_float2(w.z, w.w);
            float4 xa = *(const float4*)(s17 + c);
            float4 xb = *(const float4*)(s17 + 128 + c);
            float4 xc = *(const float4*)(s17 + 256 + c);
            float4 xd = *(const float4*)(s17 + 384 + c);
            fma2(a0, make_float2(xa.x, xa.y), wlo);
            fma2(a0, make_float2(xa.z, xa.w), whi);
            fma2(a1, make_float2(xb.x, xb.y), wlo);
            fma2(a1, make_float2(xb.z, xb.w), whi);
            fma2(a2, make_float2(xc.x, xc.y), wlo);
            fma2(a2, make_float2(xc.z, xc.w), whi);
            fma2(a3, make_float2(xd.x, xd.y), wlo);
            fma2(a3, make_float2(xd.z, xd.w), whi);
        }
        zz[0] = a0.x + a0.y; zz[1] = a1.x + a1.y;
        zz[2] = a2.x + a2.y; zz[3] = a3.x + a3.y;
        {
            float m[4], r[4];
            block_ln4(zz, sred, lane, warp4, bar, m, r);
            #pragma unroll
            for (int k = 0; k < 4; k++)
                s18[k*128 + t] = mishf((zz[k] - m[k]) * r[k] * sG3[t] + sB3[t]);
        }
        barg(bar);

        a0 = make_float2(0.f,0.f); a1 = make_float2(0.f,0.f);
        a2 = make_float2(0.f,0.f); a3 = make_float2(0.f,0.f);
        #pragma unroll 8
        for (int c = 0; c < 128; c += 4) {
            float4 w  = *(const float4*)(wr3 + c);
            float2 wlo = make_float2(w.x, w.y), whi = make_float2(w.z, w.w);
            float4 xa = *(const float4*)(s18 + c);
            float4 xb = *(const float4*)(s18 + 128 + c);
            float4 xc = *(const float4*)(s18 + 256 + c);
            float4 xd = *(const float4*)(s18 + 384 + c);
            fma2(a0, make_float2(xa.x, xa.y), wlo);
            fma2(a0, make_float2(xa.z, xa.w), whi);
            fma2(a1, make_float2(xb.x, xb.y), wlo);
            fma2(a1, make_float2(xb.z, xb.w), whi);
            fma2(a2, make_float2(xc.x, xc.y), wlo);
            fma2(a2, make_float2(xc.z, xc.w), whi);
            fma2(a3, make_float2(xd.x, xd.y), wlo);
            fma2(a3, make_float2(xd.z, xd.w), whi);
        }
        zz[0] = a0.x + a0.y; zz[1] = a1.x + a1.y;
        zz[2] = a2.x + a2.y; zz[3] = a3.x + a3.y;
        {
            float m[4], r[4];
            block_ln4(zz, sred, lane, warp4, bar, m, r);
            #pragma unroll
            for (int k = 0; k < 4; k++) {
                float x19 = mishf((zz[k] - m[k]) * r[k] * sG3[t] + sB3[t]) + x17[k];
                int2 cc = ((const int2*)bevcoors)[n0 + k];
                out[t*OUTWH + cc.y*BH + cc.x] = x19;
            }
        }
    }
}

// ============================================================================
// launch
// ============================================================================
extern "C" void kernel_launch(void* const* d_in, const int* in_sizes, int n_in,
                              void* d_out, int out_size)
{
    (void)in_sizes; (void)n_in; (void)out_size;

    const float* voxels    = (const float*)d_in[0];
    const float* voxelmask = (const float*)d_in[1];
    const int*   bevsidx   = (const int*)d_in[2];
    const int*   bevcoors  = (const int*)d_in[3];
    const float* bevmask   = (const float*)d_in[4];
    float* out = (float*)d_out;

    cudaFuncSetAttribute(vfe_kernel,  cudaFuncAttributeMaxDynamicSharedMemorySize, A_SMEM_BYTES);
    cudaFuncSetAttribute(bev2_kernel, cudaFuncAttributeMaxDynamicSharedMemorySize, B2_SMEM_BYTES);

    vfe_kernel<<<NV/(2*VFE_IT), 256, A_SMEM_BYTES>>>(
        voxels, voxelmask,
        (const float*)d_in[5],  (const float*)d_in[6],  (const float*)d_in[7],
        (const float*)d_in[8],  (const float*)d_in[9],  (const float*)d_in[10],
        (const float*)d_in[11], (const float*)d_in[12], (const float*)d_in[13],
        (const float*)d_in[14], (const float*)d_in[15], (const float*)d_in[16],
        (float4*)out);

    bev1_kernel<<<dim3(250, 16), 128>>>(
        bevsidx, bevmask,
        (const float*)d_in[17], (const float*)d_in[18], (const float*)d_in[19],
        (const float*)d_in[20], (const float*)d_in[21], (const float*)d_in[22]);

    bev2_kernel<<<1000, 256, B2_SMEM_BYTES>>>(
        (const float*)d_in[23], (const float*)d_in[24], (const float*)d_in[25],
        (const float*)d_in[26], (const float*)d_in[27], (const float*)d_in[28],
        bevcoors, out);
}